// round 1
// baseline (speedup 1.0000x reference)
#include <cuda_runtime.h>
#include <cstdint>

// 2D Haar DWT, fp32, input (8, 64, 512, 512) -> 4x (8, 64, 256, 256)
// Output d_out = [ll | lh | hl | hh], each 8*64*256*256 floats.
//
// Pure memory-bound: 512 MiB in + 512 MiB out. Strategy: 128-bit coalesced
// loads (float4 spanning 4 input columns), 64-bit coalesced stores per subband.

#define PLANES      512          // 8 * 64
#define IN_W        512
#define IN_H        512
#define OUT_W       256
#define OUT_H       256
#define PLANE_IN_F4   (IN_W * IN_H / 4)    // 65536 float4 per input plane
#define ROW_IN_F4     (IN_W / 4)           // 128 float4 per input row
#define PLANE_OUT_F2  (OUT_W * OUT_H / 2)  // 32768 float2 per output plane
#define ROW_OUT_F2    (OUT_W / 2)          // 128 float2 per output row
#define SUBBAND_ELEMS (PLANES * OUT_W * OUT_H)  // 33554432 floats per subband

__global__ __launch_bounds__(256)
void dwt2d_haar_kernel(const float4* __restrict__ x4,
                       float2* __restrict__ ll,
                       float2* __restrict__ lh,
                       float2* __restrict__ hl,
                       float2* __restrict__ hh)
{
    // One thread = one (plane, out_row, out_col_pair): reads 2x4 input patch,
    // writes 2 output pixels to each of the 4 subbands.
    unsigned tid = blockIdx.x * blockDim.x + threadIdx.x;
    // total = 512 planes * 256 rows * 128 col-pairs = 16,777,216 (exact grid)

    unsigned ox2 = tid & (ROW_OUT_F2 - 1);          // 0..127
    unsigned t1  = tid >> 7;
    unsigned oy  = t1 & (OUT_H - 1);                // 0..255
    unsigned p   = t1 >> 8;                         // 0..511

    unsigned in_base = p * PLANE_IN_F4 + (2u * oy) * ROW_IN_F4 + ox2;
    float4 r0 = x4[in_base];                // row 2y,   cols 4*ox2 .. 4*ox2+3
    float4 r1 = x4[in_base + ROW_IN_F4];    // row 2y+1

    // pixel 0: a=x[2y][2x] b=x[2y][2x+1] c=x[2y+1][2x] d=x[2y+1][2x+1]
    float a0 = r0.x, b0 = r0.y, c0 = r1.x, d0 = r1.y;
    float a1 = r0.z, b1 = r0.w, c1 = r1.z, d1 = r1.w;

    const float half = 0.5f;
    float2 vll, vlh, vhl, vhh;
    vll.x = (a0 + b0 + c0 + d0) * half;
    vll.y = (a1 + b1 + c1 + d1) * half;
    vlh.x = (c0 + d0 - a0 - b0) * half;
    vlh.y = (c1 + d1 - a1 - b1) * half;
    vhl.x = (b0 + d0 - a0 - c0) * half;
    vhl.y = (b1 + d1 - a1 - c1) * half;
    vhh.x = (a0 + d0 - b0 - c0) * half;
    vhh.y = (a1 + d1 - b1 - c1) * half;

    unsigned o = p * PLANE_OUT_F2 + oy * ROW_OUT_F2 + ox2;
    ll[o] = vll;
    lh[o] = vlh;
    hl[o] = vhl;
    hh[o] = vhh;
}

extern "C" void kernel_launch(void* const* d_in, const int* in_sizes, int n_in,
                              void* d_out, int out_size)
{
    const float4* x4 = (const float4*)d_in[0];
    float* out = (float*)d_out;

    float2* ll = (float2*)(out + 0ull * SUBBAND_ELEMS);
    float2* lh = (float2*)(out + 1ull * SUBBAND_ELEMS);
    float2* hl = (float2*)(out + 2ull * SUBBAND_ELEMS);
    float2* hh = (float2*)(out + 3ull * SUBBAND_ELEMS);

    const unsigned total_threads = PLANES * OUT_H * ROW_OUT_F2;  // 16,777,216
    const unsigned block = 256;
    const unsigned grid = total_threads / block;                 // 65,536

    dwt2d_haar_kernel<<<grid, block>>>(x4, ll, lh, hl, hh);
}